// round 13
// baseline (speedup 1.0000x reference)
#include <cuda_runtime.h>
#include <cuda_fp16.h>
#include <cstdint>

// Problem constants
#define B_SZ    1024
#define NE_SZ   100000
#define NE_PAD  100096          // 782 * 128
#define NTILES  782
#define D_SZ    200
#define KPAD    256             // row stride of packed operands (elements)

// Scratch
__device__ float   g_F2T[D_SZ * D_SZ];
__device__ __half  g_Hcat[B_SZ * KPAD];                 // 0.5 MB (pad cols stay 0)
__device__ __half  g_Ecat[(size_t)NE_PAD * KPAD];       // 51.2 MB

// ---------------------------------------------------------------------------
// PTX helpers (baseline sm_80-class PTX — compiles for plain sm_103)
// ---------------------------------------------------------------------------
__device__ __forceinline__ uint32_t smem_u32(const void* p) {
    uint32_t a;
    asm("{ .reg .u64 t; cvta.to.shared.u64 t, %1; cvt.u32.u64 %0, t; }"
        : "=r"(a) : "l"(p));
    return a;
}

__device__ __forceinline__ void cp_async16(uint32_t dst, const void* src) {
    asm volatile("cp.async.cg.shared.global [%0], [%1], 16;"
                 :: "r"(dst), "l"(src) : "memory");
}

__device__ __forceinline__ void ldsm4(uint32_t& r0, uint32_t& r1,
                                      uint32_t& r2, uint32_t& r3,
                                      uint32_t addr) {
    asm volatile("ldmatrix.sync.aligned.m8n8.x4.shared.b16 {%0,%1,%2,%3}, [%4];"
                 : "=r"(r0), "=r"(r1), "=r"(r2), "=r"(r3) : "r"(addr));
}

__device__ __forceinline__ void mma16816(float* c,
                                         uint32_t a0, uint32_t a1,
                                         uint32_t a2, uint32_t a3,
                                         uint32_t b0, uint32_t b1) {
    asm volatile(
        "mma.sync.aligned.m16n8k16.row.col.f32.f16.f16.f32 "
        "{%0,%1,%2,%3}, {%4,%5,%6,%7}, {%8,%9}, {%0,%1,%2,%3};"
        : "+f"(c[0]), "+f"(c[1]), "+f"(c[2]), "+f"(c[3])
        : "r"(a0), "r"(a1), "r"(a2), "r"(a3), "r"(b0), "r"(b1));
}

__device__ __forceinline__ uint32_t swz(uint32_t off) {
    return off ^ ((off >> 3) & 0x70);
}

// sigmoid(x) = 0.5*tanh(0.5x) + 0.5 : 1 MUFU + fma-pipe ops
__device__ __forceinline__ float fast_sigmoid(float x) {
    float t;
    asm("tanh.approx.f32 %0, %1;" : "=f"(t) : "f"(x * 0.5f));
    return fmaf(0.5f, t, 0.5f);
}

#define GROUP_BAR(id) \
    asm volatile("bar.sync %0, %1;" :: "r"(id), "r"(128) : "memory")

// ---------------------------------------------------------------------------
// Kernel 0: F2T[p][j] = F2[j][p]  (tiny; must precede the combined kernel)
// ---------------------------------------------------------------------------
#define TR_BLOCKS ((D_SZ * D_SZ + 255) / 256)                // 157

__global__ __launch_bounds__(256)
void transpose_f2_kernel(const float* __restrict__ F2, float* __restrict__ F2T)
{
    int idx = blockIdx.x * 256 + threadIdx.x;
    if (idx < D_SZ * D_SZ) {
        int p = idx / D_SZ;
        int j = idx - p * D_SZ;
        F2T[idx] = F2[j * D_SZ + p];
    }
}

// ---------------------------------------------------------------------------
// Kernel 1: COMBINED preproc (blocks 0..127) + pack E (remaining blocks).
// The two tasks are independent; one launch lets them fill the chip together.
// ---------------------------------------------------------------------------
#define PPR 8
#define PP_BLOCKS (B_SZ / PPR)                               // 128
#define KCH 26   // 208/8 column-chunks per row of Ecat
#define PK_BLOCKS ((int)(((size_t)NE_PAD * KCH) / 256))      // 10166 exact

__global__ __launch_bounds__(256)
void combined_prep_kernel(const int* __restrict__ e1_idx,
                          const int* __restrict__ r_idx,
                          const int* __restrict__ t_idx,
                          const float* __restrict__ E,
                          const float* __restrict__ R,
                          const float* __restrict__ T,
                          const float* __restrict__ F0,
                          const float* __restrict__ F1,
                          const float* __restrict__ F3,
                          const float* __restrict__ F2T,
                          __half* __restrict__ Hcat,
                          __half* __restrict__ Ecat)
{
    __shared__ float sR[PPR][D_SZ];
    __shared__ float sE[PPR][D_SZ];
    __shared__ float sT[PPR][D_SZ];
    __shared__ float sG[PPR][D_SZ];

    const int tid = threadIdx.x;

    if (blockIdx.x >= PP_BLOCKS) {
        // ---------------- pack E path ----------------
        size_t t = (size_t)(blockIdx.x - PP_BLOCKS) * 256 + tid;
        int row = (int)(t / KCH);
        int k0  = (int)(t % KCH) * 8;
        __half* dst = Ecat + (size_t)row * KPAD + k0;
        if (row < NE_SZ && k0 < D_SZ) {
            float4 x0 = *reinterpret_cast<const float4*>(E + (size_t)row * D_SZ + k0);
            float4 x1 = *reinterpret_cast<const float4*>(E + (size_t)row * D_SZ + k0 + 4);
            __half o[8] = {
                __float2half_rn(x0.x), __float2half_rn(x0.y),
                __float2half_rn(x0.z), __float2half_rn(x0.w),
                __float2half_rn(x1.x), __float2half_rn(x1.y),
                __float2half_rn(x1.z), __float2half_rn(x1.w)};
            *reinterpret_cast<uint4*>(dst) = *reinterpret_cast<uint4*>(o);
        } else {
            *reinterpret_cast<uint4*>(dst) = make_uint4(0, 0, 0, 0);
        }
        return;
    }

    // ---------------- preproc path (8 rows per block) ----------------
    const int b0   = blockIdx.x * PPR;
    const int warp = tid >> 5;
    const int lane = tid & 31;

    // load the 8 embedding rows (one warp per row)
    {
        const int r  = warp;
        const int be = e1_idx[b0 + r];
        const int br = r_idx[b0 + r];
        const int bt = t_idx[b0 + r];
        for (int k = lane; k < D_SZ; k += 32) {
            sE[r][k] = E[(size_t)be * D_SZ + k];
            sR[r][k] = R[(size_t)br * D_SZ + k];
            sT[r][k] = T[(size_t)bt * D_SZ + k];
        }
    }
    __syncthreads();

    // G phase: warp w handles p-chunk w; each F load feeds 8 rows
    if (warp < 7) {
        const int p  = warp * 32 + lane;
        const bool ok = (p < D_SZ);
        const int pc = ok ? p : 0;
        float aR[PPR], aE[PPR], aT[PPR];
        #pragma unroll
        for (int r = 0; r < PPR; r++) { aR[r] = 0.f; aE[r] = 0.f; aT[r] = 0.f; }
        #pragma unroll 4
        for (int k = 0; k < D_SZ; k++) {
            const float f0 = F0[k * D_SZ + pc];
            const float f1 = F1[k * D_SZ + pc];
            const float f3 = F3[k * D_SZ + pc];
            #pragma unroll
            for (int r = 0; r < PPR; r++) {
                aR[r] = fmaf(sR[r][k], f0, aR[r]);
                aE[r] = fmaf(sE[r][k], f1, aE[r]);
                aT[r] = fmaf(sT[r][k], f3, aT[r]);
            }
        }
        if (ok) {
            #pragma unroll
            for (int r = 0; r < PPR; r++)
                sG[r][p] = aR[r] * aE[r] * aT[r];
        }
    }
    __syncthreads();

    // H phase: warp w handles j-chunk w; each F2T load feeds 8 rows
    if (warp < 7) {
        const int j  = warp * 32 + lane;
        const bool ok = (j < D_SZ);
        const int jc = ok ? j : 0;
        float a[PPR];
        #pragma unroll
        for (int r = 0; r < PPR; r++) a[r] = 0.f;
        #pragma unroll 4
        for (int p = 0; p < D_SZ; p++) {
            const float f2 = F2T[p * D_SZ + jc];
            #pragma unroll
            for (int r = 0; r < PPR; r++)
                a[r] = fmaf(sG[r][p], f2, a[r]);
        }
        if (ok) {
            #pragma unroll
            for (int r = 0; r < PPR; r++)
                Hcat[(size_t)(b0 + r) * KPAD + j] = __float2half_rn(a[r]);
        }
    }
}

// ---------------------------------------------------------------------------
// Kernel 2: x = sigmoid(Hcat @ Ecat^T), warp-level fp16 mma.sync.
// A-resident; two independent 4-warp groups with private B rings + named
// barriers. NTPC=4 -> 1568 CTAs = 5.3 waves (shorter ramp-down tail).
// Output stores use evict-first (.cs) to keep Ecat strips resident in L2.
// ---------------------------------------------------------------------------
#define NTPC      4
#define NGRP      196                // 196*4 = 784 >= 782 (2 clamped dups)
#define A_BYTES   (4 * 16384)        // 64 KB (4 chunk slots of 128 rows x 128B)
#define BG_STAGE  8192               // 64 rows x 128B per group stage
#define SMEM_GEMM (A_BYTES + 2 * 3 * BG_STAGE)   // 112 KB -> 2 CTAs/SM

__device__ __forceinline__ void load_B_g(uint32_t sB,
                                         const __half* __restrict__ Ec,
                                         int nrow0, int kt, int ltid)
{
    const char* base = (const char*)Ec + (size_t)nrow0 * (KPAD * 2) + kt * 128;
    if (kt < 3) {
        #pragma unroll
        for (int i = 0; i < 4; i++) {          // 64 rows x 8 chunks
            int task = ltid + i * 128;
            int row = task >> 3, ch = task & 7;
            cp_async16(sB + swz(row * 128 + ch * 16),
                       base + (size_t)row * (KPAD * 2) + ch * 16);
        }
    } else {                                   // partial: 64 rows x 2 chunks
        int row = ltid >> 1, ch = ltid & 1;
        cp_async16(sB + swz(row * 128 + ch * 16),
                   base + (size_t)row * (KPAD * 2) + ch * 16);
    }
    asm volatile("cp.async.commit_group;" ::: "memory");
}

__global__ __launch_bounds__(256, 2)
void gemm_mma_kernel(const __half* __restrict__ Hc,
                     const __half* __restrict__ Ec,
                     float* __restrict__ out)
{
    extern __shared__ char smem[];
    const uint32_t sb     = smem_u32(smem);
    const uint32_t sAbase = sb;

    const int tid   = threadIdx.x;
    const int wid   = tid >> 5;
    const int lane  = tid & 31;
    const int group = wid >> 2;            // 0 or 1
    const int gwid  = wid & 3;
    const int ltid  = tid & 127;
    const int warp_m = gwid & 1;
    const int warp_n = gwid >> 1;
    const int m0 = blockIdx.x * 128;
    const int gy = blockIdx.y;
    const int nbar = 1 + group;

    const uint32_t sBg = sb + A_BYTES + group * (3 * BG_STAGE);

    // ---- A resident load: chunks 0-2 full + chunk 3 slots {0,1} (52 KB) ----
    #pragma unroll
    for (int i = 0; i < 13; i++) {
        int task = tid + i * 256;          // 0..3327
        int ktc, r, ch;
        if (task < 3072) { ktc = task >> 10; r = (task >> 3) & 127; ch = task & 7; }
        else             { int t2 = task - 3072; ktc = 3; r = t2 >> 1; ch = t2 & 1; }
        cp_async16(sAbase + ktc * 16384 + swz(r * 128 + ch * 16),
                   (const char*)Hc + (size_t)(m0 + r) * (KPAD * 2) + ktc * 128 + ch * 16);
    }
    asm volatile("cp.async.commit_group;" ::: "memory");

    // ---- B prologue: chunks 0,1 of first tile (group-local half) ----
    {
        int nt0 = gy * NTPC;           if (nt0 > NTILES - 1) nt0 = NTILES - 1;
        const int nrow0 = nt0 * 128 + group * 64;
        load_B_g(sBg + 0 * BG_STAGE, Ec, nrow0, 0, ltid);
        load_B_g(sBg + 1 * BG_STAGE, Ec, nrow0, 1, ltid);
    }

    asm volatile("cp.async.wait_group 2;" ::: "memory");
    __syncthreads();

    // fragment addressing (within-chunk byte offsets)
    uint32_t aRowOff[4], aSwb[4];
    {
        const int rbase = warp_m * 64 + (lane & 15);
        #pragma unroll
        for (int mt = 0; mt < 4; mt++) {
            int row = rbase + mt * 16;
            aRowOff[mt] = row * 128;
            aSwb[mt]    = (row & 7) * 16;
        }
    }
    const uint32_t aKhalf = (lane >> 4) * 16;

    uint32_t bRowOff[2], bSwb[2];
    {
        const int rbase = warp_n * 32 + ((lane >> 4) << 3) + (lane & 7);
        #pragma unroll
        for (int g = 0; g < 2; g++) {
            int row = rbase + g * 16;
            bRowOff[g] = row * 128;
            bSwb[g]    = (row & 7) * 16;
        }
    }
    const uint32_t bKhalf = ((lane >> 3) & 1) * 16;

    float acc[4][4][4];
    #pragma unroll
    for (int mt = 0; mt < 4; mt++)
        #pragma unroll
        for (int nt = 0; nt < 4; nt++)
            #pragma unroll
            for (int r = 0; r < 4; r++) acc[mt][nt][r] = 0.f;

    const int mBase = m0 + warp_m * 64 + (lane >> 2);
    const int nOff  = warp_n * 32 + (lane & 3) * 2;

    #pragma unroll 1
    for (int tile = 0; tile < NTPC; tile++) {
        #pragma unroll
        for (int kt = 0; kt < 4; kt++) {
            const int c = tile * 4 + kt;

            if (c < NTPC * 4 - 1)
                asm volatile("cp.async.wait_group 1;" ::: "memory");
            else
                asm volatile("cp.async.wait_group 0;" ::: "memory");
            GROUP_BAR(nbar);

            if (c + 2 < NTPC * 4) {
                const int c2 = c + 2;
                int nt2 = gy * NTPC + (c2 >> 2);
                if (nt2 > NTILES - 1) nt2 = NTILES - 1;
                load_B_g(sBg + (c2 % 3) * BG_STAGE, Ec,
                         nt2 * 128 + group * 64, c2 & 3, ltid);
            }

            const uint32_t sAc = sAbase + kt * 16384;
            const uint32_t sBc = sBg + (c % 3) * BG_STAGE;
            const int nks = (kt < 3) ? 4 : 1;

            uint32_t bbuf[2][2][4];
            #pragma unroll
            for (int g = 0; g < 2; g++)
                ldsm4(bbuf[0][g][0], bbuf[0][g][1], bbuf[0][g][2], bbuf[0][g][3],
                      sBc + bRowOff[g] + (bKhalf ^ bSwb[g]));

            #pragma unroll
            for (int ks = 0; ks < nks; ks++) {
                if (ks + 1 < nks) {
                    const uint32_t kcn = (ks + 1) * 32;
                    #pragma unroll
                    for (int g = 0; g < 2; g++)
                        ldsm4(bbuf[(ks + 1) & 1][g][0], bbuf[(ks + 1) & 1][g][1],
                              bbuf[(ks + 1) & 1][g][2], bbuf[(ks + 1) & 1][g][3],
                              sBc + bRowOff[g] + ((kcn + bKhalf) ^ bSwb[g]));
                }

                const uint32_t kcol = ks * 32;
                uint32_t a[4][4];
                #pragma unroll
                for (int mt = 0; mt < 4; mt++)
                    ldsm4(a[mt][0], a[mt][1], a[mt][2], a[mt][3],
                          sAc + aRowOff[mt] + ((kcol + aKhalf) ^ aSwb[mt]));

                const int pb = ks & 1;
                #pragma unroll
                for (int mt = 0; mt < 4; mt++)
                    #pragma unroll
                    for (int nt = 0; nt < 4; nt++)
                        mma16816(acc[mt][nt],
                                 a[mt][0], a[mt][1], a[mt][2], a[mt][3],
                                 bbuf[pb][nt >> 1][(nt & 1) * 2],
                                 bbuf[pb][nt >> 1][(nt & 1) * 2 + 1]);
            }
        }

        // ---- epilogue for this tile (streaming stores, evict-first) ----
        {
            int ntile = gy * NTPC + tile;
            if (ntile > NTILES - 1) ntile = NTILES - 1;
            const int n0 = ntile * 128 + group * 64;
            #pragma unroll
            for (int mt = 0; mt < 4; mt++) {
                #pragma unroll
                for (int nt = 0; nt < 4; nt++) {
                    const int n = n0 + nOff + nt * 8;
                    if (n < NE_SZ) {
                        const int m = mBase + mt * 16;
                        float2 v0, v1;
                        v0.x = fast_sigmoid(acc[mt][nt][0]);
                        v0.y = fast_sigmoid(acc[mt][nt][1]);
                        v1.x = fast_sigmoid(acc[mt][nt][2]);
                        v1.y = fast_sigmoid(acc[mt][nt][3]);
                        __stcs(reinterpret_cast<float2*>(out + (size_t)m * NE_SZ + n), v0);
                        __stcs(reinterpret_cast<float2*>(out + (size_t)(m + 8) * NE_SZ + n), v1);
                    }
                    #pragma unroll
                    for (int r = 0; r < 4; r++) acc[mt][nt][r] = 0.f;
                }
            }
        }
    }
}

// ---------------------------------------------------------------------------
// Launch. Inputs: e1_idx, r_idx, t_idx, E, R, T, F0, F1, F2, F3
// ---------------------------------------------------------------------------
extern "C" void kernel_launch(void* const* d_in, const int* in_sizes, int n_in,
                              void* d_out, int out_size)
{
    const int*   e1_idx = (const int*)d_in[0];
    const int*   r_idx  = (const int*)d_in[1];
    const int*   t_idx  = (const int*)d_in[2];
    const float* E      = (const float*)d_in[3];
    const float* R      = (const float*)d_in[4];
    const float* T      = (const float*)d_in[5];
    const float* F0     = (const float*)d_in[6];
    const float* F1     = (const float*)d_in[7];
    const float* F2     = (const float*)d_in[8];
    const float* F3     = (const float*)d_in[9];
    float*       out    = (float*)d_out;

    float* F2T;
    __half *Hcat, *Ecat;
    cudaGetSymbolAddress((void**)&F2T,  g_F2T);
    cudaGetSymbolAddress((void**)&Hcat, g_Hcat);
    cudaGetSymbolAddress((void**)&Ecat, g_Ecat);

    static bool attr_set = false;
    if (!attr_set) {
        cudaFuncSetAttribute(gemm_mma_kernel,
                             cudaFuncAttributeMaxDynamicSharedMemorySize,
                             SMEM_GEMM);
        attr_set = true;
    }

    transpose_f2_kernel<<<TR_BLOCKS, 256>>>(F2, F2T);

    combined_prep_kernel<<<PP_BLOCKS + PK_BLOCKS, 256>>>(
        e1_idx, r_idx, t_idx, E, R, T, F0, F1, F3, F2T, Hcat, Ecat);

    dim3 grid(B_SZ / 128, NGRP);   // (8, 196), m fastest
    gemm_mma_kernel<<<grid, 256, SMEM_GEMM>>>(Hcat, Ecat, out);
}

// round 14
// speedup vs baseline: 1.0699x; 1.0699x over previous
#include <cuda_runtime.h>
#include <cuda_fp16.h>
#include <cstdint>

// Problem constants
#define B_SZ    1024
#define NE_SZ   100000
#define NE_PAD  100096          // 782 * 128
#define NTILES  782
#define D_SZ    200
#define KPAD    256             // row stride of packed operands (elements)

// Scratch
__device__ __half  g_Hcat[B_SZ * KPAD];                 // 0.5 MB (pad cols stay 0)
__device__ __half  g_Ecat[(size_t)NE_PAD * KPAD];       // 51.2 MB

// ---------------------------------------------------------------------------
// PTX helpers (baseline sm_80-class PTX — compiles for plain sm_103)
// ---------------------------------------------------------------------------
__device__ __forceinline__ uint32_t smem_u32(const void* p) {
    uint32_t a;
    asm("{ .reg .u64 t; cvta.to.shared.u64 t, %1; cvt.u32.u64 %0, t; }"
        : "=r"(a) : "l"(p));
    return a;
}

__device__ __forceinline__ void cp_async16(uint32_t dst, const void* src) {
    asm volatile("cp.async.cg.shared.global [%0], [%1], 16;"
                 :: "r"(dst), "l"(src) : "memory");
}

__device__ __forceinline__ void ldsm4(uint32_t& r0, uint32_t& r1,
                                      uint32_t& r2, uint32_t& r3,
                                      uint32_t addr) {
    asm volatile("ldmatrix.sync.aligned.m8n8.x4.shared.b16 {%0,%1,%2,%3}, [%4];"
                 : "=r"(r0), "=r"(r1), "=r"(r2), "=r"(r3) : "r"(addr));
}

__device__ __forceinline__ void mma16816(float* c,
                                         uint32_t a0, uint32_t a1,
                                         uint32_t a2, uint32_t a3,
                                         uint32_t b0, uint32_t b1) {
    asm volatile(
        "mma.sync.aligned.m16n8k16.row.col.f32.f16.f16.f32 "
        "{%0,%1,%2,%3}, {%4,%5,%6,%7}, {%8,%9}, {%0,%1,%2,%3};"
        : "+f"(c[0]), "+f"(c[1]), "+f"(c[2]), "+f"(c[3])
        : "r"(a0), "r"(a1), "r"(a2), "r"(a3), "r"(b0), "r"(b1));
}

__device__ __forceinline__ uint32_t swz(uint32_t off) {
    return off ^ ((off >> 3) & 0x70);
}

// sigmoid(x) = 0.5*tanh(0.5x) + 0.5 : 1 MUFU + fma-pipe ops
__device__ __forceinline__ float fast_sigmoid(float x) {
    float t;
    asm("tanh.approx.f32 %0, %1;" : "=f"(t) : "f"(x * 0.5f));
    return fmaf(0.5f, t, 0.5f);
}

#define GROUP_BAR(id) \
    asm volatile("bar.sync %0, %1;" :: "r"(id), "r"(128) : "memory")

// ---------------------------------------------------------------------------
// Kernel 1: COMBINED preproc (blocks 0..127) + pack E (remaining blocks).
// No F2T dependency: the H phase reads F2 rows directly (contiguous per lane,
// L2-resident, reused by all 128 preproc blocks) -> both halves of this
// kernel are fully independent and fill the chip together in ONE launch.
// ---------------------------------------------------------------------------
#define PPR 8
#define PP_BLOCKS (B_SZ / PPR)                               // 128
#define KCH 26   // 208/8 column-chunks per row of Ecat
#define PK_BLOCKS ((int)(((size_t)NE_PAD * KCH) / 256))      // 10166 exact

__global__ __launch_bounds__(256)
void combined_prep_kernel(const int* __restrict__ e1_idx,
                          const int* __restrict__ r_idx,
                          const int* __restrict__ t_idx,
                          const float* __restrict__ E,
                          const float* __restrict__ R,
                          const float* __restrict__ T,
                          const float* __restrict__ F0,
                          const float* __restrict__ F1,
                          const float* __restrict__ F2,
                          const float* __restrict__ F3,
                          __half* __restrict__ Hcat,
                          __half* __restrict__ Ecat)
{
    __shared__ float sR[PPR][D_SZ];
    __shared__ float sE[PPR][D_SZ];
    __shared__ float sT[PPR][D_SZ];
    __shared__ float sG[PPR][D_SZ];

    const int tid = threadIdx.x;

    if (blockIdx.x >= PP_BLOCKS) {
        // ---------------- pack E path ----------------
        size_t t = (size_t)(blockIdx.x - PP_BLOCKS) * 256 + tid;
        int row = (int)(t / KCH);
        int k0  = (int)(t % KCH) * 8;
        __half* dst = Ecat + (size_t)row * KPAD + k0;
        if (row < NE_SZ && k0 < D_SZ) {
            float4 x0 = *reinterpret_cast<const float4*>(E + (size_t)row * D_SZ + k0);
            float4 x1 = *reinterpret_cast<const float4*>(E + (size_t)row * D_SZ + k0 + 4);
            __half o[8] = {
                __float2half_rn(x0.x), __float2half_rn(x0.y),
                __float2half_rn(x0.z), __float2half_rn(x0.w),
                __float2half_rn(x1.x), __float2half_rn(x1.y),
                __float2half_rn(x1.z), __float2half_rn(x1.w)};
            *reinterpret_cast<uint4*>(dst) = *reinterpret_cast<uint4*>(o);
        } else {
            *reinterpret_cast<uint4*>(dst) = make_uint4(0, 0, 0, 0);
        }
        return;
    }

    // ---------------- preproc path (8 rows per block) ----------------
    const int b0   = blockIdx.x * PPR;
    const int warp = tid >> 5;
    const int lane = tid & 31;

    // load the 8 embedding rows (one warp per row)
    {
        const int r  = warp;
        const int be = e1_idx[b0 + r];
        const int br = r_idx[b0 + r];
        const int bt = t_idx[b0 + r];
        for (int k = lane; k < D_SZ; k += 32) {
            sE[r][k] = E[(size_t)be * D_SZ + k];
            sR[r][k] = R[(size_t)br * D_SZ + k];
            sT[r][k] = T[(size_t)bt * D_SZ + k];
        }
    }
    __syncthreads();

    // G phase: warp w handles p-chunk w (coalesced F columns, 8-row reuse)
    if (warp < 7) {
        const int p  = warp * 32 + lane;
        const bool ok = (p < D_SZ);
        const int pc = ok ? p : 0;
        float aR[PPR], aE[PPR], aT[PPR];
        #pragma unroll
        for (int r = 0; r < PPR; r++) { aR[r] = 0.f; aE[r] = 0.f; aT[r] = 0.f; }
        #pragma unroll 4
        for (int k = 0; k < D_SZ; k++) {
            const float f0 = F0[k * D_SZ + pc];
            const float f1 = F1[k * D_SZ + pc];
            const float f3 = F3[k * D_SZ + pc];
            #pragma unroll
            for (int r = 0; r < PPR; r++) {
                aR[r] = fmaf(sR[r][k], f0, aR[r]);
                aE[r] = fmaf(sE[r][k], f1, aE[r]);
                aT[r] = fmaf(sT[r][k], f3, aT[r]);
            }
        }
        if (ok) {
            #pragma unroll
            for (int r = 0; r < PPR; r++)
                sG[r][p] = aR[r] * aE[r] * aT[r];
        }
    }
    __syncthreads();

    // H phase: lane owns column j and streams F2 row j (contiguous float4,
    // L2-resident, shared across all preproc blocks). sG reads broadcast.
    if (warp < 7) {
        const int j  = warp * 32 + lane;
        const bool ok = (j < D_SZ);
        const int jc = ok ? j : 0;
        const float4* f2row = reinterpret_cast<const float4*>(F2 + (size_t)jc * D_SZ);
        float a[PPR];
        #pragma unroll
        for (int r = 0; r < PPR; r++) a[r] = 0.f;
        #pragma unroll 5
        for (int p4 = 0; p4 < D_SZ / 4; p4++) {
            const float4 f = f2row[p4];
            const int p = p4 * 4;
            #pragma unroll
            for (int r = 0; r < PPR; r++) {
                a[r] = fmaf(sG[r][p + 0], f.x, a[r]);
                a[r] = fmaf(sG[r][p + 1], f.y, a[r]);
                a[r] = fmaf(sG[r][p + 2], f.z, a[r]);
                a[r] = fmaf(sG[r][p + 3], f.w, a[r]);
            }
        }
        if (ok) {
            #pragma unroll
            for (int r = 0; r < PPR; r++)
                Hcat[(size_t)(b0 + r) * KPAD + j] = __float2half_rn(a[r]);
        }
    }
}

// ---------------------------------------------------------------------------
// Kernel 2: x = sigmoid(Hcat @ Ecat^T), warp-level fp16 mma.sync.
// EXACT R12 configuration (best measured): A-resident, two independent
// 4-warp groups with private B rings + named barriers, NTPC=7, NGRP=112,
// plain float2 stores.
// ---------------------------------------------------------------------------
#define NTPC      7
#define NGRP      112                // 112*7 = 784 >= 782 (2 clamped dups)
#define A_BYTES   (4 * 16384)        // 64 KB (4 chunk slots of 128 rows x 128B)
#define BG_STAGE  8192               // 64 rows x 128B per group stage
#define SMEM_GEMM (A_BYTES + 2 * 3 * BG_STAGE)   // 112 KB -> 2 CTAs/SM

__device__ __forceinline__ void load_B_g(uint32_t sB,
                                         const __half* __restrict__ Ec,
                                         int nrow0, int kt, int ltid)
{
    const char* base = (const char*)Ec + (size_t)nrow0 * (KPAD * 2) + kt * 128;
    if (kt < 3) {
        #pragma unroll
        for (int i = 0; i < 4; i++) {          // 64 rows x 8 chunks
            int task = ltid + i * 128;
            int row = task >> 3, ch = task & 7;
            cp_async16(sB + swz(row * 128 + ch * 16),
                       base + (size_t)row * (KPAD * 2) + ch * 16);
        }
    } else {                                   // partial: 64 rows x 2 chunks
        int row = ltid >> 1, ch = ltid & 1;
        cp_async16(sB + swz(row * 128 + ch * 16),
                   base + (size_t)row * (KPAD * 2) + ch * 16);
    }
    asm volatile("cp.async.commit_group;" ::: "memory");
}

__global__ __launch_bounds__(256, 2)
void gemm_mma_kernel(const __half* __restrict__ Hc,
                     const __half* __restrict__ Ec,
                     float* __restrict__ out)
{
    extern __shared__ char smem[];
    const uint32_t sb     = smem_u32(smem);
    const uint32_t sAbase = sb;

    const int tid   = threadIdx.x;
    const int wid   = tid >> 5;
    const int lane  = tid & 31;
    const int group = wid >> 2;            // 0 or 1
    const int gwid  = wid & 3;
    const int ltid  = tid & 127;
    const int warp_m = gwid & 1;
    const int warp_n = gwid >> 1;
    const int m0 = blockIdx.x * 128;
    const int gy = blockIdx.y;
    const int nbar = 1 + group;

    const uint32_t sBg = sb + A_BYTES + group * (3 * BG_STAGE);

    // ---- A resident load: chunks 0-2 full + chunk 3 slots {0,1} (52 KB) ----
    #pragma unroll
    for (int i = 0; i < 13; i++) {
        int task = tid + i * 256;          // 0..3327
        int ktc, r, ch;
        if (task < 3072) { ktc = task >> 10; r = (task >> 3) & 127; ch = task & 7; }
        else             { int t2 = task - 3072; ktc = 3; r = t2 >> 1; ch = t2 & 1; }
        cp_async16(sAbase + ktc * 16384 + swz(r * 128 + ch * 16),
                   (const char*)Hc + (size_t)(m0 + r) * (KPAD * 2) + ktc * 128 + ch * 16);
    }
    asm volatile("cp.async.commit_group;" ::: "memory");

    // ---- B prologue: chunks 0,1 of first tile (group-local half) ----
    {
        int nt0 = gy * NTPC;           if (nt0 > NTILES - 1) nt0 = NTILES - 1;
        const int nrow0 = nt0 * 128 + group * 64;
        load_B_g(sBg + 0 * BG_STAGE, Ec, nrow0, 0, ltid);
        load_B_g(sBg + 1 * BG_STAGE, Ec, nrow0, 1, ltid);
    }

    asm volatile("cp.async.wait_group 2;" ::: "memory");
    __syncthreads();

    // fragment addressing (within-chunk byte offsets)
    uint32_t aRowOff[4], aSwb[4];
    {
        const int rbase = warp_m * 64 + (lane & 15);
        #pragma unroll
        for (int mt = 0; mt < 4; mt++) {
            int row = rbase + mt * 16;
            aRowOff[mt] = row * 128;
            aSwb[mt]    = (row & 7) * 16;
        }
    }
    const uint32_t aKhalf = (lane >> 4) * 16;

    uint32_t bRowOff[2], bSwb[2];
    {
        const int rbase = warp_n * 32 + ((lane >> 4) << 3) + (lane & 7);
        #pragma unroll
        for (int g = 0; g < 2; g++) {
            int row = rbase + g * 16;
            bRowOff[g] = row * 128;
            bSwb[g]    = (row & 7) * 16;
        }
    }
    const uint32_t bKhalf = ((lane >> 3) & 1) * 16;

    float acc[4][4][4];
    #pragma unroll
    for (int mt = 0; mt < 4; mt++)
        #pragma unroll
        for (int nt = 0; nt < 4; nt++)
            #pragma unroll
            for (int r = 0; r < 4; r++) acc[mt][nt][r] = 0.f;

    const int mBase = m0 + warp_m * 64 + (lane >> 2);
    const int nOff  = warp_n * 32 + (lane & 3) * 2;

    #pragma unroll 1
    for (int tile = 0; tile < NTPC; tile++) {
        #pragma unroll
        for (int kt = 0; kt < 4; kt++) {
            const int c = tile * 4 + kt;

            if (c < NTPC * 4 - 1)
                asm volatile("cp.async.wait_group 1;" ::: "memory");
            else
                asm volatile("cp.async.wait_group 0;" ::: "memory");
            GROUP_BAR(nbar);

            if (c + 2 < NTPC * 4) {
                const int c2 = c + 2;
                int nt2 = gy * NTPC + (c2 >> 2);
                if (nt2 > NTILES - 1) nt2 = NTILES - 1;
                load_B_g(sBg + (c2 % 3) * BG_STAGE, Ec,
                         nt2 * 128 + group * 64, c2 & 3, ltid);
            }

            const uint32_t sAc = sAbase + kt * 16384;
            const uint32_t sBc = sBg + (c % 3) * BG_STAGE;
            const int nks = (kt < 3) ? 4 : 1;

            uint32_t bbuf[2][2][4];
            #pragma unroll
            for (int g = 0; g < 2; g++)
                ldsm4(bbuf[0][g][0], bbuf[0][g][1], bbuf[0][g][2], bbuf[0][g][3],
                      sBc + bRowOff[g] + (bKhalf ^ bSwb[g]));

            #pragma unroll
            for (int ks = 0; ks < nks; ks++) {
                if (ks + 1 < nks) {
                    const uint32_t kcn = (ks + 1) * 32;
                    #pragma unroll
                    for (int g = 0; g < 2; g++)
                        ldsm4(bbuf[(ks + 1) & 1][g][0], bbuf[(ks + 1) & 1][g][1],
                              bbuf[(ks + 1) & 1][g][2], bbuf[(ks + 1) & 1][g][3],
                              sBc + bRowOff[g] + ((kcn + bKhalf) ^ bSwb[g]));
                }

                const uint32_t kcol = ks * 32;
                uint32_t a[4][4];
                #pragma unroll
                for (int mt = 0; mt < 4; mt++)
                    ldsm4(a[mt][0], a[mt][1], a[mt][2], a[mt][3],
                          sAc + aRowOff[mt] + ((kcol + aKhalf) ^ aSwb[mt]));

                const int pb = ks & 1;
                #pragma unroll
                for (int mt = 0; mt < 4; mt++)
                    #pragma unroll
                    for (int nt = 0; nt < 4; nt++)
                        mma16816(acc[mt][nt],
                                 a[mt][0], a[mt][1], a[mt][2], a[mt][3],
                                 bbuf[pb][nt >> 1][(nt & 1) * 2],
                                 bbuf[pb][nt >> 1][(nt & 1) * 2 + 1]);
            }
        }

        // ---- epilogue for this tile ----
        {
            int ntile = gy * NTPC + tile;
            if (ntile > NTILES - 1) ntile = NTILES - 1;
            const int n0 = ntile * 128 + group * 64;
            #pragma unroll
            for (int mt = 0; mt < 4; mt++) {
                #pragma unroll
                for (int nt = 0; nt < 4; nt++) {
                    const int n = n0 + nOff + nt * 8;
                    if (n < NE_SZ) {
                        const int m = mBase + mt * 16;
                        float2 v0, v1;
                        v0.x = fast_sigmoid(acc[mt][nt][0]);
                        v0.y = fast_sigmoid(acc[mt][nt][1]);
                        v1.x = fast_sigmoid(acc[mt][nt][2]);
                        v1.y = fast_sigmoid(acc[mt][nt][3]);
                        *reinterpret_cast<float2*>(out + (size_t)m * NE_SZ + n)       = v0;
                        *reinterpret_cast<float2*>(out + (size_t)(m + 8) * NE_SZ + n) = v1;
                    }
                    #pragma unroll
                    for (int r = 0; r < 4; r++) acc[mt][nt][r] = 0.f;
                }
            }
        }
    }
}

// ---------------------------------------------------------------------------
// Launch. Inputs: e1_idx, r_idx, t_idx, E, R, T, F0, F1, F2, F3
// ---------------------------------------------------------------------------
extern "C" void kernel_launch(void* const* d_in, const int* in_sizes, int n_in,
                              void* d_out, int out_size)
{
    const int*   e1_idx = (const int*)d_in[0];
    const int*   r_idx  = (const int*)d_in[1];
    const int*   t_idx  = (const int*)d_in[2];
    const float* E      = (const float*)d_in[3];
    const float* R      = (const float*)d_in[4];
    const float* T      = (const float*)d_in[5];
    const float* F0     = (const float*)d_in[6];
    const float* F1     = (const float*)d_in[7];
    const float* F2     = (const float*)d_in[8];
    const float* F3     = (const float*)d_in[9];
    float*       out    = (float*)d_out;

    __half *Hcat, *Ecat;
    cudaGetSymbolAddress((void**)&Hcat, g_Hcat);
    cudaGetSymbolAddress((void**)&Ecat, g_Ecat);

    static bool attr_set = false;
    if (!attr_set) {
        cudaFuncSetAttribute(gemm_mma_kernel,
                             cudaFuncAttributeMaxDynamicSharedMemorySize,
                             SMEM_GEMM);
        attr_set = true;
    }

    combined_prep_kernel<<<PP_BLOCKS + PK_BLOCKS, 256>>>(
        e1_idx, r_idx, t_idx, E, R, T, F0, F1, F2, F3, Hcat, Ecat);

    dim3 grid(B_SZ / 128, NGRP);   // (8, 112), m fastest
    gemm_mma_kernel<<<grid, 256, SMEM_GEMM>>>(Hcat, Ecat, out);
}

// round 15
// speedup vs baseline: 1.0754x; 1.0052x over previous
#include <cuda_runtime.h>
#include <cuda_fp16.h>
#include <cstdint>

// Problem constants
#define B_SZ    1024
#define NE_SZ   100000
#define NE_PAD  100096          // 782 * 128
#define NTILES  782
#define D_SZ    200
#define KPAD    256             // row stride of packed operands (elements)

// Scratch
__device__ __half  g_Hcat[B_SZ * KPAD];                 // 0.5 MB (pad cols stay 0)
__device__ __half  g_Ecat[(size_t)NE_PAD * KPAD];       // 51.2 MB

// ---------------------------------------------------------------------------
// PTX helpers (baseline sm_80-class PTX — compiles for plain sm_103)
// ---------------------------------------------------------------------------
__device__ __forceinline__ uint32_t smem_u32(const void* p) {
    uint32_t a;
    asm("{ .reg .u64 t; cvta.to.shared.u64 t, %1; cvt.u32.u64 %0, t; }"
        : "=r"(a) : "l"(p));
    return a;
}

__device__ __forceinline__ void cp_async16(uint32_t dst, const void* src) {
    asm volatile("cp.async.cg.shared.global [%0], [%1], 16;"
                 :: "r"(dst), "l"(src) : "memory");
}

__device__ __forceinline__ void ldsm4(uint32_t& r0, uint32_t& r1,
                                      uint32_t& r2, uint32_t& r3,
                                      uint32_t addr) {
    asm volatile("ldmatrix.sync.aligned.m8n8.x4.shared.b16 {%0,%1,%2,%3}, [%4];"
                 : "=r"(r0), "=r"(r1), "=r"(r2), "=r"(r3) : "r"(addr));
}

__device__ __forceinline__ void mma16816(float* c,
                                         uint32_t a0, uint32_t a1,
                                         uint32_t a2, uint32_t a3,
                                         uint32_t b0, uint32_t b1) {
    asm volatile(
        "mma.sync.aligned.m16n8k16.row.col.f32.f16.f16.f32 "
        "{%0,%1,%2,%3}, {%4,%5,%6,%7}, {%8,%9}, {%0,%1,%2,%3};"
        : "+f"(c[0]), "+f"(c[1]), "+f"(c[2]), "+f"(c[3])
        : "r"(a0), "r"(a1), "r"(a2), "r"(a3), "r"(b0), "r"(b1));
}

__device__ __forceinline__ uint32_t swz(uint32_t off) {
    return off ^ ((off >> 3) & 0x70);
}

// sigmoid(x) = 0.5*tanh(0.5x) + 0.5 : 1 MUFU + fma-pipe ops
__device__ __forceinline__ float fast_sigmoid(float x) {
    float t;
    asm("tanh.approx.f32 %0, %1;" : "=f"(t) : "f"(x * 0.5f));
    return fmaf(0.5f, t, 0.5f);
}

// ---------------------------------------------------------------------------
// Kernel 1: COMBINED preproc (blocks 0..127) + pack E (remaining blocks).
// (Unchanged from R14 — measured good.)
// ---------------------------------------------------------------------------
#define PPR 8
#define PP_BLOCKS (B_SZ / PPR)                               // 128
#define KCH 26   // 208/8 column-chunks per row of Ecat
#define PK_BLOCKS ((int)(((size_t)NE_PAD * KCH) / 256))      // 10166 exact

__global__ __launch_bounds__(256)
void combined_prep_kernel(const int* __restrict__ e1_idx,
                          const int* __restrict__ r_idx,
                          const int* __restrict__ t_idx,
                          const float* __restrict__ E,
                          const float* __restrict__ R,
                          const float* __restrict__ T,
                          const float* __restrict__ F0,
                          const float* __restrict__ F1,
                          const float* __restrict__ F2,
                          const float* __restrict__ F3,
                          __half* __restrict__ Hcat,
                          __half* __restrict__ Ecat)
{
    __shared__ float sR[PPR][D_SZ];
    __shared__ float sE[PPR][D_SZ];
    __shared__ float sT[PPR][D_SZ];
    __shared__ float sG[PPR][D_SZ];

    const int tid = threadIdx.x;

    if (blockIdx.x >= PP_BLOCKS) {
        // ---------------- pack E path ----------------
        size_t t = (size_t)(blockIdx.x - PP_BLOCKS) * 256 + tid;
        int row = (int)(t / KCH);
        int k0  = (int)(t % KCH) * 8;
        __half* dst = Ecat + (size_t)row * KPAD + k0;
        if (row < NE_SZ && k0 < D_SZ) {
            float4 x0 = *reinterpret_cast<const float4*>(E + (size_t)row * D_SZ + k0);
            float4 x1 = *reinterpret_cast<const float4*>(E + (size_t)row * D_SZ + k0 + 4);
            __half o[8] = {
                __float2half_rn(x0.x), __float2half_rn(x0.y),
                __float2half_rn(x0.z), __float2half_rn(x0.w),
                __float2half_rn(x1.x), __float2half_rn(x1.y),
                __float2half_rn(x1.z), __float2half_rn(x1.w)};
            *reinterpret_cast<uint4*>(dst) = *reinterpret_cast<uint4*>(o);
        } else {
            *reinterpret_cast<uint4*>(dst) = make_uint4(0, 0, 0, 0);
        }
        return;
    }

    // ---------------- preproc path (8 rows per block) ----------------
    const int b0   = blockIdx.x * PPR;
    const int warp = tid >> 5;
    const int lane = tid & 31;

    {
        const int r  = warp;
        const int be = e1_idx[b0 + r];
        const int br = r_idx[b0 + r];
        const int bt = t_idx[b0 + r];
        for (int k = lane; k < D_SZ; k += 32) {
            sE[r][k] = E[(size_t)be * D_SZ + k];
            sR[r][k] = R[(size_t)br * D_SZ + k];
            sT[r][k] = T[(size_t)bt * D_SZ + k];
        }
    }
    __syncthreads();

    if (warp < 7) {
        const int p  = warp * 32 + lane;
        const bool ok = (p < D_SZ);
        const int pc = ok ? p : 0;
        float aR[PPR], aE[PPR], aT[PPR];
        #pragma unroll
        for (int r = 0; r < PPR; r++) { aR[r] = 0.f; aE[r] = 0.f; aT[r] = 0.f; }
        #pragma unroll 4
        for (int k = 0; k < D_SZ; k++) {
            const float f0 = F0[k * D_SZ + pc];
            const float f1 = F1[k * D_SZ + pc];
            const float f3 = F3[k * D_SZ + pc];
            #pragma unroll
            for (int r = 0; r < PPR; r++) {
                aR[r] = fmaf(sR[r][k], f0, aR[r]);
                aE[r] = fmaf(sE[r][k], f1, aE[r]);
                aT[r] = fmaf(sT[r][k], f3, aT[r]);
            }
        }
        if (ok) {
            #pragma unroll
            for (int r = 0; r < PPR; r++)
                sG[r][p] = aR[r] * aE[r] * aT[r];
        }
    }
    __syncthreads();

    if (warp < 7) {
        const int j  = warp * 32 + lane;
        const bool ok = (j < D_SZ);
        const int jc = ok ? j : 0;
        const float4* f2row = reinterpret_cast<const float4*>(F2 + (size_t)jc * D_SZ);
        float a[PPR];
        #pragma unroll
        for (int r = 0; r < PPR; r++) a[r] = 0.f;
        #pragma unroll 5
        for (int p4 = 0; p4 < D_SZ / 4; p4++) {
            const float4 f = f2row[p4];
            const int p = p4 * 4;
            #pragma unroll
            for (int r = 0; r < PPR; r++) {
                a[r] = fmaf(sG[r][p + 0], f.x, a[r]);
                a[r] = fmaf(sG[r][p + 1], f.y, a[r]);
                a[r] = fmaf(sG[r][p + 2], f.z, a[r]);
                a[r] = fmaf(sG[r][p + 3], f.w, a[r]);
            }
        }
        if (ok) {
            #pragma unroll
            for (int r = 0; r < PPR; r++)
                Hcat[(size_t)(b0 + r) * KPAD + j] = __float2half_rn(a[r]);
        }
    }
}

// ---------------------------------------------------------------------------
// Kernel 2: x = sigmoid(Hcat @ Ecat^T), warp-level fp16 mma.sync.
// BARRIER-FREE mainloop: each warp owns a private 2-stage B ring (its 32
// n-rows x 128B slice) fed by its own cp.async stream — producer==consumer,
// so no bar.sync after the prologue. A chunks 0-2 CTA-resident in smem
// (48 KB); kt=3 A fragments hoisted to registers (reused all 7 tiles).
// warp_m pairs duplicate B staging (+crossbar/L2, affordable) to buy the
// full decoupling. NTPC=7, NGRP=112 (R12/R14-proven schedule).
// ---------------------------------------------------------------------------
#define NTPC      7
#define NGRP      112                // 112*7 = 784 >= 782 (2 clamped dups)
#define A_BYTES   (3 * 16384)        // 48 KB: A chunks 0-2
#define W_STAGE   4096               // 32 rows x 128B per warp stage
#define SMEM_GEMM (A_BYTES + 8 * 2 * W_STAGE)   // 112 KB -> 2 CTAs/SM

// per-warp B chunk issue: 32 rows of this warp's n-slice, chunk kt
__device__ __forceinline__ void issueB_w(uint32_t sB,
                                         const __half* __restrict__ Ec,
                                         int nrow0, int kt, int lane)
{
    const char* base = (const char*)Ec + (size_t)nrow0 * (KPAD * 2) + kt * 128;
    if (kt < 3) {
        #pragma unroll
        for (int i = 0; i < 8; i++) {          // 32 rows x 8 chunks of 16B
            int task = lane + i * 32;
            int row = task >> 3, ch = task & 7;
            cp_async16(sB + swz(row * 128 + ch * 16),
                       base + (size_t)row * (KPAD * 2) + ch * 16);
        }
    } else {                                   // partial: 32 rows x 2 chunks
        #pragma unroll
        for (int i = 0; i < 2; i++) {
            int task = lane + i * 32;
            int row = task >> 1, ch = task & 1;
            cp_async16(sB + swz(row * 128 + ch * 16),
                       base + (size_t)row * (KPAD * 2) + ch * 16);
        }
    }
    asm volatile("cp.async.commit_group;" ::: "memory");
}

__global__ __launch_bounds__(256, 2)
void gemm_mma_kernel(const __half* __restrict__ Hc,
                     const __half* __restrict__ Ec,
                     float* __restrict__ out)
{
    extern __shared__ char smem[];
    const uint32_t sb     = smem_u32(smem);
    const uint32_t sBbase = sb + A_BYTES;

    const int tid    = threadIdx.x;
    const int wid    = tid >> 5;
    const int lane   = tid & 31;
    const int warp_m = wid & 1;            // m half (64 rows)
    const int wslice = wid >> 1;           // 0..3 : n slice of 32 within tile
    const int m0 = blockIdx.x * 128;
    const int gy = blockIdx.y;

    const uint32_t sBw = sBbase + wid * (2 * W_STAGE);   // this warp's 2 stages

    // ---- prologue: A chunks 0-2 (48 KB) + kt3-A temp (4 KB at sBbase) ----
    #pragma unroll
    for (int i = 0; i < 12; i++) {
        int task = tid + i * 256;          // 0..3071
        int ktc = task >> 10, r = (task >> 3) & 127, ch = task & 7;
        cp_async16(sb + ktc * 16384 + swz(r * 128 + ch * 16),
                   (const char*)Hc + (size_t)(m0 + r) * (KPAD * 2) + ktc * 128 + ch * 16);
    }
    {   // temp: 128 rows x 32B (cols 192..207)
        int r = tid >> 1, ch = tid & 1;
        cp_async16(sBbase + r * 32 + ch * 16,
                   (const char*)Hc + (size_t)(m0 + r) * (KPAD * 2) + 384 + ch * 16);
    }
    asm volatile("cp.async.commit_group;" ::: "memory");
    asm volatile("cp.async.wait_group 0;" ::: "memory");
    __syncthreads();

    // fragment addressing (within-chunk byte offsets)
    uint32_t aRowOff[4], aSwb[4];
    {
        const int rbase = warp_m * 64 + (lane & 15);
        #pragma unroll
        for (int mt = 0; mt < 4; mt++) {
            int row = rbase + mt * 16;
            aRowOff[mt] = row * 128;
            aSwb[mt]    = (row & 7) * 16;
        }
    }
    const uint32_t aKhalf = (lane >> 4) * 16;

    uint32_t bRowOff[2], bSwb[2];
    {
        const int rbase = ((lane >> 4) << 3) + (lane & 7);   // rows within 32-slice
        #pragma unroll
        for (int g = 0; g < 2; g++) {
            int row = rbase + g * 16;
            bRowOff[g] = row * 128;
            bSwb[g]    = (row & 7) * 16;
        }
    }
    const uint32_t bKhalf = ((lane >> 3) & 1) * 16;

    // kt=3 A fragments from temp -> registers (reused all tiles)
    uint32_t a3[4][4];
    {
        const int rbase = warp_m * 64 + (lane & 15);
        #pragma unroll
        for (int mt = 0; mt < 4; mt++) {
            int row = rbase + mt * 16;
            ldsm4(a3[mt][0], a3[mt][1], a3[mt][2], a3[mt][3],
                  sBbase + row * 32 + aKhalf);
        }
    }
    __syncthreads();   // all warps done with temp before B staging overwrites

    float acc[4][4][4];
    #pragma unroll
    for (int mt = 0; mt < 4; mt++)
        #pragma unroll
        for (int nt = 0; nt < 4; nt++)
            #pragma unroll
            for (int r = 0; r < 4; r++) acc[mt][nt][r] = 0.f;

    const int mBase = m0 + warp_m * 64 + (lane >> 2);
    const int nOffL = (lane & 3) * 2;

    // issue chunk 0 (this warp's slice)
    {
        int nt0 = gy * NTPC; if (nt0 > NTILES - 1) nt0 = NTILES - 1;
        issueB_w(sBw, Ec, nt0 * 128 + wslice * 32, 0, lane);
    }

    #pragma unroll 1
    for (int tile = 0; tile < NTPC; tile++) {
        #pragma unroll
        for (int kt = 0; kt < 4; kt++) {
            const int c = tile * 4 + kt;

            if (c + 1 < NTPC * 4) {
                const int c2 = c + 1;
                int nt2 = gy * NTPC + (c2 >> 2);
                if (nt2 > NTILES - 1) nt2 = NTILES - 1;
                issueB_w(sBw + (c2 & 1) * W_STAGE, Ec,
                         nt2 * 128 + wslice * 32, c2 & 3, lane);
                asm volatile("cp.async.wait_group 1;" ::: "memory");
            } else {
                asm volatile("cp.async.wait_group 0;" ::: "memory");
            }

            const uint32_t sBc = sBw + (c & 1) * W_STAGE;

            if (kt < 3) {
                const uint32_t sAc = sb + kt * 16384;
                #pragma unroll
                for (int ks = 0; ks < 4; ks++) {
                    const uint32_t kcol = ks * 32;
                    uint32_t bb[2][4];
                    #pragma unroll
                    for (int g = 0; g < 2; g++)
                        ldsm4(bb[g][0], bb[g][1], bb[g][2], bb[g][3],
                              sBc + bRowOff[g] + ((kcol + bKhalf) ^ bSwb[g]));
                    uint32_t a[4][4];
                    #pragma unroll
                    for (int mt = 0; mt < 4; mt++)
                        ldsm4(a[mt][0], a[mt][1], a[mt][2], a[mt][3],
                              sAc + aRowOff[mt] + ((kcol + aKhalf) ^ aSwb[mt]));
                    #pragma unroll
                    for (int mt = 0; mt < 4; mt++)
                        #pragma unroll
                        for (int nt = 0; nt < 4; nt++)
                            mma16816(acc[mt][nt],
                                     a[mt][0], a[mt][1], a[mt][2], a[mt][3],
                                     bb[nt >> 1][(nt & 1) * 2],
                                     bb[nt >> 1][(nt & 1) * 2 + 1]);
                }
            } else {
                // partial chunk: k16 only, A from registers
                uint32_t bb[2][4];
                #pragma unroll
                for (int g = 0; g < 2; g++)
                    ldsm4(bb[g][0], bb[g][1], bb[g][2], bb[g][3],
                          sBc + bRowOff[g] + (bKhalf ^ bSwb[g]));
                #pragma unroll
                for (int mt = 0; mt < 4; mt++)
                    #pragma unroll
                    for (int nt = 0; nt < 4; nt++)
                        mma16816(acc[mt][nt],
                                 a3[mt][0], a3[mt][1], a3[mt][2], a3[mt][3],
                                 bb[nt >> 1][(nt & 1) * 2],
                                 bb[nt >> 1][(nt & 1) * 2 + 1]);
            }
        }

        // ---- epilogue for this tile (no syncs; overlaps other warps) ----
        {
            int ntile = gy * NTPC + tile;
            if (ntile > NTILES - 1) ntile = NTILES - 1;
            const int n0 = ntile * 128 + wslice * 32;
            #pragma unroll
            for (int mt = 0; mt < 4; mt++) {
                #pragma unroll
                for (int nt = 0; nt < 4; nt++) {
                    const int n = n0 + nOffL + nt * 8;
                    if (n < NE_SZ) {
                        const int m = mBase + mt * 16;
                        float2 v0, v1;
                        v0.x = fast_sigmoid(acc[mt][nt][0]);
                        v0.y = fast_sigmoid(acc[mt][nt][1]);
                        v1.x = fast_sigmoid(acc[mt][nt][2]);
                        v1.y = fast_sigmoid(acc[mt][nt][3]);
                        *reinterpret_cast<float2*>(out + (size_t)m * NE_SZ + n)       = v0;
                        *reinterpret_cast<float2*>(out + (size_t)(m + 8) * NE_SZ + n) = v1;
                    }
                    #pragma unroll
                    for (int r = 0; r < 4; r++) acc[mt][nt][r] = 0.f;
                }
            }
        }
    }
}

// ---------------------------------------------------------------------------
// Launch. Inputs: e1_idx, r_idx, t_idx, E, R, T, F0, F1, F2, F3
// ---------------------------------------------------------------------------
extern "C" void kernel_launch(void* const* d_in, const int* in_sizes, int n_in,
                              void* d_out, int out_size)
{
    const int*   e1_idx = (const int*)d_in[0];
    const int*   r_idx  = (const int*)d_in[1];
    const int*   t_idx  = (const int*)d_in[2];
    const float* E      = (const float*)d_in[3];
    const float* R      = (const float*)d_in[4];
    const float* T      = (const float*)d_in[5];
    const float* F0     = (const float*)d_in[6];
    const float* F1     = (const float*)d_in[7];
    const float* F2     = (const float*)d_in[8];
    const float* F3     = (const float*)d_in[9];
    float*       out    = (float*)d_out;

    __half *Hcat, *Ecat;
    cudaGetSymbolAddress((void**)&Hcat, g_Hcat);
    cudaGetSymbolAddress((void**)&Ecat, g_Ecat);

    static bool attr_set = false;
    if (!attr_set) {
        cudaFuncSetAttribute(gemm_mma_kernel,
                             cudaFuncAttributeMaxDynamicSharedMemorySize,
                             SMEM_GEMM);
        attr_set = true;
    }

    combined_prep_kernel<<<PP_BLOCKS + PK_BLOCKS, 256>>>(
        e1_idx, r_idx, t_idx, E, R, T, F0, F1, F2, F3, Hcat, Ecat);

    dim3 grid(B_SZ / 128, NGRP);   // (8, 112), m fastest
    gemm_mma_kernel<<<grid, 256, SMEM_GEMM>>>(Hcat, Ecat, out);
}

// round 16
// speedup vs baseline: 1.1171x; 1.0387x over previous
#include <cuda_runtime.h>
#include <cuda_fp16.h>
#include <cstdint>

// Problem constants
#define B_SZ    1024
#define NE_SZ   100000
#define NE_PAD  100096          // 782 * 128
#define NTILES  782
#define D_SZ    200
#define KPAD    256             // row stride of packed operands (elements)

// Scratch
__device__ __half  g_Hcat[B_SZ * KPAD];                 // 0.5 MB (pad cols stay 0)
__device__ __half  g_Ecat[(size_t)NE_PAD * KPAD];       // 51.2 MB

// ---------------------------------------------------------------------------
// PTX helpers (baseline sm_80-class PTX — compiles for plain sm_103)
// ---------------------------------------------------------------------------
__device__ __forceinline__ uint32_t smem_u32(const void* p) {
    uint32_t a;
    asm("{ .reg .u64 t; cvta.to.shared.u64 t, %1; cvt.u32.u64 %0, t; }"
        : "=r"(a) : "l"(p));
    return a;
}

__device__ __forceinline__ void cp_async16(uint32_t dst, const void* src) {
    asm volatile("cp.async.cg.shared.global [%0], [%1], 16;"
                 :: "r"(dst), "l"(src) : "memory");
}

__device__ __forceinline__ void ldsm4(uint32_t& r0, uint32_t& r1,
                                      uint32_t& r2, uint32_t& r3,
                                      uint32_t addr) {
    asm volatile("ldmatrix.sync.aligned.m8n8.x4.shared.b16 {%0,%1,%2,%3}, [%4];"
                 : "=r"(r0), "=r"(r1), "=r"(r2), "=r"(r3) : "r"(addr));
}

__device__ __forceinline__ void mma16816(float* c,
                                         uint32_t a0, uint32_t a1,
                                         uint32_t a2, uint32_t a3,
                                         uint32_t b0, uint32_t b1) {
    asm volatile(
        "mma.sync.aligned.m16n8k16.row.col.f32.f16.f16.f32 "
        "{%0,%1,%2,%3}, {%4,%5,%6,%7}, {%8,%9}, {%0,%1,%2,%3};"
        : "+f"(c[0]), "+f"(c[1]), "+f"(c[2]), "+f"(c[3])
        : "r"(a0), "r"(a1), "r"(a2), "r"(a3), "r"(b0), "r"(b1));
}

__device__ __forceinline__ uint32_t swz(uint32_t off) {
    return off ^ ((off >> 3) & 0x70);
}

// sigmoid(x) = 0.5*tanh(0.5x) + 0.5 : 1 MUFU + fma-pipe ops
__device__ __forceinline__ float fast_sigmoid(float x) {
    float t;
    asm("tanh.approx.f32 %0, %1;" : "=f"(t) : "f"(x * 0.5f));
    return fmaf(0.5f, t, 0.5f);
}

// ---------------------------------------------------------------------------
// Kernel 1: COMBINED preproc (blocks 0..255) + pack E (remaining blocks).
// PPR=4: shorter per-block serial chain so the preproc tail hides fully
// under the DRAM-bound pack-E stream.
// ---------------------------------------------------------------------------
#define PPR 4
#define PP_BLOCKS (B_SZ / PPR)                               // 256
#define KCH 26   // 208/8 column-chunks per row of Ecat
#define PK_BLOCKS ((int)(((size_t)NE_PAD * KCH) / 256))      // 10166 exact

__global__ __launch_bounds__(256)
void combined_prep_kernel(const int* __restrict__ e1_idx,
                          const int* __restrict__ r_idx,
                          const int* __restrict__ t_idx,
                          const float* __restrict__ E,
                          const float* __restrict__ R,
                          const float* __restrict__ T,
                          const float* __restrict__ F0,
                          const float* __restrict__ F1,
                          const float* __restrict__ F2,
                          const float* __restrict__ F3,
                          __half* __restrict__ Hcat,
                          __half* __restrict__ Ecat)
{
    __shared__ float sR[PPR][D_SZ];
    __shared__ float sE[PPR][D_SZ];
    __shared__ float sT[PPR][D_SZ];
    __shared__ float sG[PPR][D_SZ];

    const int tid = threadIdx.x;

    if (blockIdx.x >= PP_BLOCKS) {
        // ---------------- pack E path ----------------
        size_t t = (size_t)(blockIdx.x - PP_BLOCKS) * 256 + tid;
        int row = (int)(t / KCH);
        int k0  = (int)(t % KCH) * 8;
        __half* dst = Ecat + (size_t)row * KPAD + k0;
        if (row < NE_SZ && k0 < D_SZ) {
            float4 x0 = *reinterpret_cast<const float4*>(E + (size_t)row * D_SZ + k0);
            float4 x1 = *reinterpret_cast<const float4*>(E + (size_t)row * D_SZ + k0 + 4);
            __half o[8] = {
                __float2half_rn(x0.x), __float2half_rn(x0.y),
                __float2half_rn(x0.z), __float2half_rn(x0.w),
                __float2half_rn(x1.x), __float2half_rn(x1.y),
                __float2half_rn(x1.z), __float2half_rn(x1.w)};
            *reinterpret_cast<uint4*>(dst) = *reinterpret_cast<uint4*>(o);
        } else {
            *reinterpret_cast<uint4*>(dst) = make_uint4(0, 0, 0, 0);
        }
        return;
    }

    // ---------------- preproc path (4 rows per block) ----------------
    const int b0   = blockIdx.x * PPR;
    const int warp = tid >> 5;
    const int lane = tid & 31;

    for (int r = 0; r < PPR; r++) {
        const int be = e1_idx[b0 + r];
        const int br = r_idx[b0 + r];
        const int bt = t_idx[b0 + r];
        for (int k = tid; k < D_SZ; k += 256) {
            sE[r][k] = E[(size_t)be * D_SZ + k];
            sR[r][k] = R[(size_t)br * D_SZ + k];
            sT[r][k] = T[(size_t)bt * D_SZ + k];
        }
    }
    __syncthreads();

    if (warp < 7) {
        const int p  = warp * 32 + lane;
        const bool ok = (p < D_SZ);
        const int pc = ok ? p : 0;
        float aR[PPR], aE[PPR], aT[PPR];
        #pragma unroll
        for (int r = 0; r < PPR; r++) { aR[r] = 0.f; aE[r] = 0.f; aT[r] = 0.f; }
        #pragma unroll 4
        for (int k = 0; k < D_SZ; k++) {
            const float f0 = F0[k * D_SZ + pc];
            const float f1 = F1[k * D_SZ + pc];
            const float f3 = F3[k * D_SZ + pc];
            #pragma unroll
            for (int r = 0; r < PPR; r++) {
                aR[r] = fmaf(sR[r][k], f0, aR[r]);
                aE[r] = fmaf(sE[r][k], f1, aE[r]);
                aT[r] = fmaf(sT[r][k], f3, aT[r]);
            }
        }
        if (ok) {
            #pragma unroll
            for (int r = 0; r < PPR; r++)
                sG[r][p] = aR[r] * aE[r] * aT[r];
        }
    }
    __syncthreads();

    if (warp < 7) {
        const int j  = warp * 32 + lane;
        const bool ok = (j < D_SZ);
        const int jc = ok ? j : 0;
        const float4* f2row = reinterpret_cast<const float4*>(F2 + (size_t)jc * D_SZ);
        float a[PPR];
        #pragma unroll
        for (int r = 0; r < PPR; r++) a[r] = 0.f;
        #pragma unroll 5
        for (int p4 = 0; p4 < D_SZ / 4; p4++) {
            const float4 f = f2row[p4];
            const int p = p4 * 4;
            #pragma unroll
            for (int r = 0; r < PPR; r++) {
                a[r] = fmaf(sG[r][p + 0], f.x, a[r]);
                a[r] = fmaf(sG[r][p + 1], f.y, a[r]);
                a[r] = fmaf(sG[r][p + 2], f.z, a[r]);
                a[r] = fmaf(sG[r][p + 3], f.w, a[r]);
            }
        }
        if (ok) {
            #pragma unroll
            for (int r = 0; r < PPR; r++)
                Hcat[(size_t)(b0 + r) * KPAD + j] = __float2half_rn(a[r]);
        }
    }
}

// ---------------------------------------------------------------------------
// Kernel 2: x = sigmoid(Hcat @ Ecat^T), warp-level fp16 mma.sync.
// R15 barrier-free structure (per-warp private 2-stage B rings, A chunks 0-2
// CTA-resident, kt3 A in registers) PLUS a smem-staged coalesced epilogue:
// at each tile end, the warp's just-freed B stage (4 KB) stages the 8 KB of
// results one mt (16 rows x 128B, pitch 144) at a time -> STG.128 at
// 128B-per-wavefront instead of STG.64 at 32B-per-wavefront.
// ---------------------------------------------------------------------------
#define NTPC      7
#define NGRP      112                // 112*7 = 784 >= 782 (2 clamped dups)
#define A_BYTES   (3 * 16384)        // 48 KB: A chunks 0-2
#define W_STAGE   4096               // 32 rows x 128B per warp stage
#define EPI_PITCH 144                // 128B row + 16B pad (conflict <= 2)
#define SMEM_GEMM (A_BYTES + 8 * 2 * W_STAGE)   // 112 KB -> 2 CTAs/SM

// per-warp B chunk issue: 32 rows of this warp's n-slice, chunk kt
__device__ __forceinline__ void issueB_w(uint32_t sB,
                                         const __half* __restrict__ Ec,
                                         int nrow0, int kt, int lane)
{
    const char* base = (const char*)Ec + (size_t)nrow0 * (KPAD * 2) + kt * 128;
    if (kt < 3) {
        #pragma unroll
        for (int i = 0; i < 8; i++) {          // 32 rows x 8 chunks of 16B
            int task = lane + i * 32;
            int row = task >> 3, ch = task & 7;
            cp_async16(sB + swz(row * 128 + ch * 16),
                       base + (size_t)row * (KPAD * 2) + ch * 16);
        }
    } else {                                   // partial: 32 rows x 2 chunks
        #pragma unroll
        for (int i = 0; i < 2; i++) {
            int task = lane + i * 32;
            int row = task >> 1, ch = task & 1;
            cp_async16(sB + swz(row * 128 + ch * 16),
                       base + (size_t)row * (KPAD * 2) + ch * 16);
        }
    }
    asm volatile("cp.async.commit_group;" ::: "memory");
}

__global__ __launch_bounds__(256, 2)
void gemm_mma_kernel(const __half* __restrict__ Hc,
                     const __half* __restrict__ Ec,
                     float* __restrict__ out)
{
    extern __shared__ char smem[];
    const uint32_t sb     = smem_u32(smem);
    const uint32_t sBbase = sb + A_BYTES;

    const int tid    = threadIdx.x;
    const int wid    = tid >> 5;
    const int lane   = tid & 31;
    const int warp_m = wid & 1;            // m half (64 rows)
    const int wslice = wid >> 1;           // 0..3 : n slice of 32 within tile
    const int m0 = blockIdx.x * 128;
    const int gy = blockIdx.y;

    const uint32_t sBw = sBbase + wid * (2 * W_STAGE);   // this warp's 2 stages

    // ---- prologue: A chunks 0-2 (48 KB) + kt3-A temp (4 KB at sBbase) ----
    #pragma unroll
    for (int i = 0; i < 12; i++) {
        int task = tid + i * 256;          // 0..3071
        int ktc = task >> 10, r = (task >> 3) & 127, ch = task & 7;
        cp_async16(sb + ktc * 16384 + swz(r * 128 + ch * 16),
                   (const char*)Hc + (size_t)(m0 + r) * (KPAD * 2) + ktc * 128 + ch * 16);
    }
    {   // temp: 128 rows x 32B (cols 192..207)
        int r = tid >> 1, ch = tid & 1;
        cp_async16(sBbase + r * 32 + ch * 16,
                   (const char*)Hc + (size_t)(m0 + r) * (KPAD * 2) + 384 + ch * 16);
    }
    asm volatile("cp.async.commit_group;" ::: "memory");
    asm volatile("cp.async.wait_group 0;" ::: "memory");
    __syncthreads();

    // fragment addressing (within-chunk byte offsets)
    uint32_t aRowOff[4], aSwb[4];
    {
        const int rbase = warp_m * 64 + (lane & 15);
        #pragma unroll
        for (int mt = 0; mt < 4; mt++) {
            int row = rbase + mt * 16;
            aRowOff[mt] = row * 128;
            aSwb[mt]    = (row & 7) * 16;
        }
    }
    const uint32_t aKhalf = (lane >> 4) * 16;

    uint32_t bRowOff[2], bSwb[2];
    {
        const int rbase = ((lane >> 4) << 3) + (lane & 7);   // rows within 32-slice
        #pragma unroll
        for (int g = 0; g < 2; g++) {
            int row = rbase + g * 16;
            bRowOff[g] = row * 128;
            bSwb[g]    = (row & 7) * 16;
        }
    }
    const uint32_t bKhalf = ((lane >> 3) & 1) * 16;

    // kt=3 A fragments from temp -> registers (reused all tiles)
    uint32_t a3[4][4];
    {
        const int rbase = warp_m * 64 + (lane & 15);
        #pragma unroll
        for (int mt = 0; mt < 4; mt++) {
            int row = rbase + mt * 16;
            ldsm4(a3[mt][0], a3[mt][1], a3[mt][2], a3[mt][3],
                  sBbase + row * 32 + aKhalf);
        }
    }
    __syncthreads();   // all warps done with temp before B staging overwrites

    float acc[4][4][4];
    #pragma unroll
    for (int mt = 0; mt < 4; mt++)
        #pragma unroll
        for (int nt = 0; nt < 4; nt++)
            #pragma unroll
            for (int r = 0; r < 4; r++) acc[mt][nt][r] = 0.f;

    const int mB    = m0 + warp_m * 64;        // + mt*16 + grp*8 + (lane>>2)
    const int q     = lane >> 2;
    const int cpair = lane & 3;

    // issue chunk 0 (this warp's slice)
    {
        int nt0 = gy * NTPC; if (nt0 > NTILES - 1) nt0 = NTILES - 1;
        issueB_w(sBw, Ec, nt0 * 128 + wslice * 32, 0, lane);
    }

    #pragma unroll 1
    for (int tile = 0; tile < NTPC; tile++) {
        #pragma unroll
        for (int kt = 0; kt < 4; kt++) {
            const int c = tile * 4 + kt;

            if (c + 1 < NTPC * 4) {
                const int c2 = c + 1;
                int nt2 = gy * NTPC + (c2 >> 2);
                if (nt2 > NTILES - 1) nt2 = NTILES - 1;
                issueB_w(sBw + (c2 & 1) * W_STAGE, Ec,
                         nt2 * 128 + wslice * 32, c2 & 3, lane);
                asm volatile("cp.async.wait_group 1;" ::: "memory");
            } else {
                asm volatile("cp.async.wait_group 0;" ::: "memory");
            }

            const uint32_t sBc = sBw + (c & 1) * W_STAGE;

            if (kt < 3) {
                const uint32_t sAc = sb + kt * 16384;
                #pragma unroll
                for (int ks = 0; ks < 4; ks++) {
                    const uint32_t kcol = ks * 32;
                    uint32_t bb[2][4];
                    #pragma unroll
                    for (int g = 0; g < 2; g++)
                        ldsm4(bb[g][0], bb[g][1], bb[g][2], bb[g][3],
                              sBc + bRowOff[g] + ((kcol + bKhalf) ^ bSwb[g]));
                    uint32_t a[4][4];
                    #pragma unroll
                    for (int mt = 0; mt < 4; mt++)
                        ldsm4(a[mt][0], a[mt][1], a[mt][2], a[mt][3],
                              sAc + aRowOff[mt] + ((kcol + aKhalf) ^ aSwb[mt]));
                    #pragma unroll
                    for (int mt = 0; mt < 4; mt++)
                        #pragma unroll
                        for (int nt = 0; nt < 4; nt++)
                            mma16816(acc[mt][nt],
                                     a[mt][0], a[mt][1], a[mt][2], a[mt][3],
                                     bb[nt >> 1][(nt & 1) * 2],
                                     bb[nt >> 1][(nt & 1) * 2 + 1]);
                }
            } else {
                // partial chunk: k16 only, A from registers
                uint32_t bb[2][4];
                #pragma unroll
                for (int g = 0; g < 2; g++)
                    ldsm4(bb[g][0], bb[g][1], bb[g][2], bb[g][3],
                          sBc + bRowOff[g] + (bKhalf ^ bSwb[g]));
                #pragma unroll
                for (int mt = 0; mt < 4; mt++)
                    #pragma unroll
                    for (int nt = 0; nt < 4; nt++)
                        mma16816(acc[mt][nt],
                                 a3[mt][0], a3[mt][1], a3[mt][2], a3[mt][3],
                                 bb[nt >> 1][(nt & 1) * 2],
                                 bb[nt >> 1][(nt & 1) * 2 + 1]);
            }
        }

        // ---- staged epilogue: through the just-freed B stage (warp-local) ----
        {
            int ntile = gy * NTPC + tile;
            if (ntile > NTILES - 1) ntile = NTILES - 1;
            const int n0w = ntile * 128 + wslice * 32;
            // stage (c&1) with c = tile*4+3 was just consumed; chunk c+1 is in
            // the other stage; chunk c+2 (same stage as this) is issued only at
            // the next loop top, after we finish here.
            const uint32_t sFree = sBw + (((tile * 4 + 3) & 1) * W_STAGE);

            #pragma unroll
            for (int mt = 0; mt < 4; mt++) {
                // STS: 16 rows (grp*8+q) x 128B, pitch EPI_PITCH
                #pragma unroll
                for (int grp = 0; grp < 2; grp++) {
                    const uint32_t rowaddr =
                        sFree + (uint32_t)(grp * 8 + q) * EPI_PITCH + cpair * 8;
                    #pragma unroll
                    for (int nt = 0; nt < 4; nt++) {
                        float vx = fast_sigmoid(acc[mt][nt][2 * grp + 0]);
                        float vy = fast_sigmoid(acc[mt][nt][2 * grp + 1]);
                        asm volatile("st.shared.v2.f32 [%0], {%1, %2};"
                                     :: "r"(rowaddr + nt * 32), "f"(vx), "f"(vy));
                    }
                }
                __syncwarp();
                // LDS.128 + STG.128: 16 rows x 128B, fully coalesced
                #pragma unroll
                for (int i = 0; i < 4; i++) {
                    const int row = i * 4 + (lane >> 3);      // 0..15 = grp*8+q
                    const int col = (lane & 7) * 4;           // float index
                    float4 val;
                    asm volatile("ld.shared.v4.f32 {%0,%1,%2,%3}, [%4];"
                        : "=f"(val.x), "=f"(val.y), "=f"(val.z), "=f"(val.w)
                        : "r"(sFree + (uint32_t)row * EPI_PITCH + col * 4));
                    const int m = mB + mt * 16 + row;
                    const int n = n0w + col;
                    if (n < NE_SZ)
                        *reinterpret_cast<float4*>(out + (size_t)m * NE_SZ + n) = val;
                }
                __syncwarp();
                #pragma unroll
                for (int nt = 0; nt < 4; nt++)
                    #pragma unroll
                    for (int r = 0; r < 4; r++) acc[mt][nt][r] = 0.f;
            }
        }
    }
}

// ---------------------------------------------------------------------------
// Launch. Inputs: e1_idx, r_idx, t_idx, E, R, T, F0, F1, F2, F3
// ---------------------------------------------------------------------------
extern "C" void kernel_launch(void* const* d_in, const int* in_sizes, int n_in,
                              void* d_out, int out_size)
{
    const int*   e1_idx = (const int*)d_in[0];
    const int*   r_idx  = (const int*)d_in[1];
    const int*   t_idx  = (const int*)d_in[2];
    const float* E      = (const float*)d_in[3];
    const float* R      = (const float*)d_in[4];
    const float* T      = (const float*)d_in[5];
    const float* F0     = (const float*)d_in[6];
    const float* F1     = (const float*)d_in[7];
    const float* F2     = (const float*)d_in[8];
    const float* F3     = (const float*)d_in[9];
    float*       out    = (float*)d_out;

    __half *Hcat, *Ecat;
    cudaGetSymbolAddress((void**)&Hcat, g_Hcat);
    cudaGetSymbolAddress((void**)&Ecat, g_Ecat);

    static bool attr_set = false;
    if (!attr_set) {
        cudaFuncSetAttribute(gemm_mma_kernel,
                             cudaFuncAttributeMaxDynamicSharedMemorySize,
                             SMEM_GEMM);
        attr_set = true;
    }

    combined_prep_kernel<<<PP_BLOCKS + PK_BLOCKS, 256>>>(
        e1_idx, r_idx, t_idx, E, R, T, F0, F1, F2, F3, Hcat, Ecat);

    dim3 grid(B_SZ / 128, NGRP);   // (8, 112), m fastest
    gemm_mma_kernel<<<grid, 256, SMEM_GEMM>>>(Hcat, Ecat, out);
}